// round 16
// baseline (speedup 1.0000x reference)
#include <cuda_runtime.h>
#include <cuda_fp16.h>
#include <math.h>

#define SEQ     1560
#define SEQ_PAD 1600
#define DIM     1536
#define NH      12
#define HD      128
#define TOTAL   9360
#define TOT_PAD 9408
#define START   7800
#define W_DIM   52
#define GIDX    5
#define CF      22
#define CHW     43

#define NSPLIT  3
#define SPLIT_T 49                 // 147 tiles = 3 x 49

// ---------------- scratch (no allocations allowed) ----------------
__device__ __align__(16) float  g_q[SEQ * DIM];
__device__ __align__(16) float  g_k[SEQ * DIM];
__device__ __align__(16) float  g_attn[SEQ * DIM];
__device__ __align__(16) float  g_xr[SEQ * DIM];
__device__ __align__(16) float  g_wvr[DIM * DIM];
__device__ __align__(16) float  g_wor[DIM * DIM];
__device__ __align__(16) float  g_po[NSPLIT * SEQ_PAD * DIM];   // partial O
__device__ __align__(16) float  g_pl[NSPLIT * NH * SEQ_PAD];    // partial l
__device__ __align__(16) __half g_xh[SEQ * DIM];
__device__ __align__(16) __half g_whq[DIM * DIM];
__device__ __align__(16) __half g_whk[DIM * DIM];
__device__ __align__(16) __half g_qh[SEQ_PAD * DIM];
__device__ __align__(16) __half g_kh[TOT_PAD * DIM];
__device__ __align__(16) __half g_vh[TOT_PAD * DIM];

// ---------------- asm helpers ----------------
__device__ __forceinline__ unsigned f2tf32(float f) {
    unsigned r; asm("cvt.rna.tf32.f32 %0, %1;" : "=r"(r) : "f"(f)); return r;
}
__device__ __forceinline__ float ex2(float x) {
    float r; asm("ex2.approx.ftz.f32 %0, %1;" : "=f"(r) : "f"(x)); return r;
}
__device__ __forceinline__ unsigned packh(float lo, float hi) {
    __half2 h = __floats2half2_rn(lo, hi);
    return *(unsigned*)&h;
}
__device__ __forceinline__ unsigned sptr(const void* p) {
    return (unsigned)__cvta_generic_to_shared(p);
}
__device__ __forceinline__ void cp16(unsigned dst, const void* src) {
    asm volatile("cp.async.cg.shared.global [%0], [%1], 16;" :: "r"(dst), "l"(src));
}
__device__ __forceinline__ void cp16z(unsigned dst, const void* src, int sz) {
    asm volatile("cp.async.cg.shared.global [%0], [%1], 16, %2;" :: "r"(dst), "l"(src), "r"(sz));
}
__device__ __forceinline__ void cp_commit() { asm volatile("cp.async.commit_group;"); }
__device__ __forceinline__ void cp_wait0() { asm volatile("cp.async.wait_group 0;"); }
__device__ __forceinline__ void ldsm_x4(unsigned& r0, unsigned& r1, unsigned& r2, unsigned& r3, unsigned a) {
    asm volatile("ldmatrix.sync.aligned.m8n8.x4.shared.b16 {%0,%1,%2,%3}, [%4];"
                 : "=r"(r0), "=r"(r1), "=r"(r2), "=r"(r3) : "r"(a));
}
__device__ __forceinline__ void ldsm_x4t(unsigned& r0, unsigned& r1, unsigned& r2, unsigned& r3, unsigned a) {
    asm volatile("ldmatrix.sync.aligned.m8n8.x4.trans.shared.b16 {%0,%1,%2,%3}, [%4];"
                 : "=r"(r0), "=r"(r1), "=r"(r2), "=r"(r3) : "r"(a));
}
__device__ __forceinline__ void mma_tf32(float* c, const unsigned* a, const unsigned* b) {
    asm volatile("mma.sync.aligned.m16n8k8.row.col.f32.tf32.tf32.f32 "
                 "{%0,%1,%2,%3}, {%4,%5,%6,%7}, {%8,%9}, {%0,%1,%2,%3};\n"
                 : "+f"(c[0]), "+f"(c[1]), "+f"(c[2]), "+f"(c[3])
                 : "r"(a[0]), "r"(a[1]), "r"(a[2]), "r"(a[3]), "r"(b[0]), "r"(b[1]));
}
__device__ __forceinline__ void mma_f16(float* c, unsigned a0, unsigned a1,
                                        unsigned a2, unsigned a3,
                                        unsigned b0, unsigned b1) {
    asm volatile("mma.sync.aligned.m16n8k16.row.col.f32.f16.f16.f32 "
                 "{%0,%1,%2,%3}, {%4,%5,%6,%7}, {%8,%9}, {%0,%1,%2,%3};\n"
                 : "+f"(c[0]), "+f"(c[1]), "+f"(c[2]), "+f"(c[3])
                 : "r"(a0), "r"(a1), "r"(a2), "r"(a3), "r"(b0), "r"(b1));
}

// ======================= fused prologue =======================
__global__ __launch_bounds__(256) void prologue(
    const float* __restrict__ x,
    const float* __restrict__ wq, const float* __restrict__ wk,
    const float* __restrict__ wv, const float* __restrict__ wo,
    const float* __restrict__ kc, const float* __restrict__ vc)
{
    const int g = blockIdx.x * 256 + threadIdx.x;
    const int stride = gridDim.x * 256;

    const int WN4 = DIM * DIM / 4;
    const int XN4 = SEQ * DIM / 4;
    const int KN4 = START * DIM / 4;

    for (int i = g; i < WN4; i += stride) {
        float4 a = ((const float4*)wv)[i];
        float4 b = ((const float4*)wo)[i];
        a.x = __uint_as_float(f2tf32(a.x)); a.y = __uint_as_float(f2tf32(a.y));
        a.z = __uint_as_float(f2tf32(a.z)); a.w = __uint_as_float(f2tf32(a.w));
        b.x = __uint_as_float(f2tf32(b.x)); b.y = __uint_as_float(f2tf32(b.y));
        b.z = __uint_as_float(f2tf32(b.z)); b.w = __uint_as_float(f2tf32(b.w));
        ((float4*)g_wvr)[i] = a;
        ((float4*)g_wor)[i] = b;
    }
    for (int i = g; i < XN4; i += stride) {
        float4 v = ((const float4*)x)[i];
        float4 r = make_float4(__uint_as_float(f2tf32(v.x)), __uint_as_float(f2tf32(v.y)),
                               __uint_as_float(f2tf32(v.z)), __uint_as_float(f2tf32(v.w)));
        ((float4*)g_xr)[i] = r;
        ((__half2*)g_xh)[2*i]   = __floats2half2_rn(v.x, v.y);
        ((__half2*)g_xh)[2*i+1] = __floats2half2_rn(v.z, v.w);
    }
    for (int i = g; i < WN4; i += stride) {
        float4 a = ((const float4*)wq)[i];
        float4 b = ((const float4*)wk)[i];
        ((__half2*)g_whq)[2*i]   = __floats2half2_rn(a.x, a.y);
        ((__half2*)g_whq)[2*i+1] = __floats2half2_rn(a.z, a.w);
        ((__half2*)g_whk)[2*i]   = __floats2half2_rn(b.x, b.y);
        ((__half2*)g_whk)[2*i+1] = __floats2half2_rn(b.z, b.w);
    }
    for (int i = g; i < KN4; i += stride) {
        float4 a = ((const float4*)kc)[i];
        float4 b = ((const float4*)vc)[i];
        ((__half2*)g_kh)[2*i]   = __floats2half2_rn(a.x, a.y);
        ((__half2*)g_kh)[2*i+1] = __floats2half2_rn(a.z, a.w);
        ((__half2*)g_vh)[2*i]   = __floats2half2_rn(b.x, b.y);
        ((__half2*)g_vh)[2*i+1] = __floats2half2_rn(b.z, b.w);
    }
    const int NQP = (SEQ_PAD - SEQ) * DIM / 8;
    const int NKP = (TOT_PAD - TOTAL) * DIM / 8;
    const uint4 z = make_uint4(0, 0, 0, 0);
    for (int i = g; i < NQP; i += stride) ((uint4*)(g_qh + (size_t)SEQ * DIM))[i] = z;
    for (int i = g; i < NKP; i += stride) {
        ((uint4*)(g_kh + (size_t)TOTAL * DIM))[i] = z;
        ((uint4*)(g_vh + (size_t)TOTAL * DIM))[i] = z;
    }
}

// ================= fused QKV GEMM (mixed fp16 / tf32) =================
#define ASTR 36
#define G_STAGE (128 * ASTR)
#define GSMEM (4 * G_STAGE * 4)
#define HSTR 40
#define H_STAGE (128 * HSTR)
#define NIT (DIM / 32)

__global__ __launch_bounds__(256) void qkv_kernel(
    const __half* __restrict__ xh,
    const __half* __restrict__ whq, const __half* __restrict__ whk,
    const float* __restrict__ xr, const float* __restrict__ wvr,
    const float* __restrict__ bq, const float* __restrict__ bk, const float* __restrict__ bv,
    float* __restrict__ outq, float* __restrict__ outk, __half* __restrict__ outv)
{
    extern __shared__ __align__(16) char dyn[];
    const int tid = threadIdx.x;
    const int bm = blockIdx.y * 128;
    const int wid = tid >> 5, lane = tid & 31;
    const int wm = (wid & 1) * 64, wn = (wid >> 1) * 32;
    const int gid = lane >> 2, tidg = lane & 3;

    float c[4][4][4];
#pragma unroll
    for (int mt = 0; mt < 4; mt++)
#pragma unroll
        for (int nt = 0; nt < 4; nt++)
#pragma unroll
            for (int i = 0; i < 4; i++) c[mt][nt][i] = 0.f;

    if (blockIdx.x < 24) {
        const int sec = blockIdx.x / 12;
        const int bnl = (blockIdx.x % 12) * 128;
        const __half* W    = sec ? whk : whq;
        const float* bias  = sec ? bk : bq;
        float* outp        = sec ? outk : outq;

        __half* smh = (__half*)dyn;
        const unsigned sA = sptr(smh);
        const unsigned sB = sA + 2 * H_STAGE * 2;

        auto load_tile = [&](int st, int k0) {
#pragma unroll
            for (int l = 0; l < 2; l++) {
                int idx = tid + 256 * l;
                int r = idx >> 2, ch = idx & 3;
                unsigned off = (unsigned)(st * H_STAGE + r * HSTR + ch * 8) * 2u;
                int gm = bm + r;
                int rowc = gm < SEQ ? gm : (SEQ - 1);
                cp16z(sA + off, xh + (size_t)rowc * DIM + k0 + ch * 8, gm < SEQ ? 16 : 0);
                cp16 (sB + off, W  + (size_t)(bnl + r) * DIM + k0 + ch * 8);
            }
            cp_commit();
        };

        const unsigned aoff = ((lane & 15) * HSTR + (lane >> 4) * 8) * 2;
        const unsigned boff = (((lane >> 4) * 8 + (lane & 7)) * HSTR + ((lane >> 3) & 1) * 8) * 2;

        load_tile(0, 0);
        for (int it = 0; it < NIT; it++) {
            cp_wait0();
            __syncthreads();
            if (it + 1 < NIT) load_tile((it + 1) & 1, (it + 1) * 32);

            const unsigned aB = sA + (unsigned)((it & 1) * H_STAGE * 2);
            const unsigned bB = sB + (unsigned)((it & 1) * H_STAGE * 2);
#pragma unroll
            for (int kf = 0; kf < 2; kf++) {
                unsigned a[4][4];
#pragma unroll
                for (int mt = 0; mt < 4; mt++)
                    ldsm_x4(a[mt][0], a[mt][1], a[mt][2], a[mt][3],
                            aB + (unsigned)(((wm + mt * 16) * HSTR + kf * 16) * 2) + aoff);
#pragma unroll
                for (int np = 0; np < 2; np++) {
                    unsigned b0, b1, b2, b3;
                    ldsm_x4(b0, b1, b2, b3,
                            bB + (unsigned)(((wn + np * 16) * HSTR + kf * 16) * 2) + boff);
#pragma unroll
                    for (int mt = 0; mt < 4; mt++) {
                        mma_f16(c[mt][2*np],   a[mt][0], a[mt][1], a[mt][2], a[mt][3], b0, b1);
                        mma_f16(c[mt][2*np+1], a[mt][0], a[mt][1], a[mt][2], a[mt][3], b2, b3);
                    }
                }
            }
        }

#pragma unroll
        for (int mt = 0; mt < 4; mt++) {
#pragma unroll
            for (int nt = 0; nt < 4; nt++) {
                int col = bnl + wn + nt * 8 + 2 * tidg;
                float b0 = bias[col], b1 = bias[col + 1];
#pragma unroll
                for (int half = 0; half < 2; half++) {
                    int r = bm + wm + mt * 16 + gid + half * 8;
                    if (r < SEQ)
                        *(float2*)(outp + (size_t)r * DIM + col) =
                            make_float2(c[mt][nt][2*half] + b0, c[mt][nt][2*half+1] + b1);
                }
            }
        }
    } else {
        const int bnl = (blockIdx.x - 24) * 128;
        float* smf = (float*)dyn;
        const unsigned sA = sptr(smf);
        const unsigned sB = sA + 2 * G_STAGE * 4;
        const int lr = tid >> 3, lc = tid & 7;

        auto load_tile = [&](int st, int k0) {
#pragma unroll
            for (int l = 0; l < 4; l++) {
                int r = lr + l * 32;
                unsigned off = (unsigned)(st * G_STAGE + r * ASTR + lc * 4) * 4u;
                int gm = bm + r;
                int rowc = gm < SEQ ? gm : (SEQ - 1);
                cp16z(sA + off, xr + (size_t)rowc * DIM + k0 + lc * 4, gm < SEQ ? 16 : 0);
                cp16 (sB + off, wvr + (size_t)(bnl + r) * DIM + k0 + lc * 4);
            }
            cp_commit();
        };

        load_tile(0, 0);
        for (int it = 0; it < NIT; it++) {
            cp_wait0();
            __syncthreads();
            if (it + 1 < NIT) load_tile((it + 1) & 1, (it + 1) * 32);

            const float* Asb = smf + (it & 1) * G_STAGE;
            const float* Bsb = smf + 2 * G_STAGE + (it & 1) * G_STAGE;
#pragma unroll
            for (int ks = 0; ks < 4; ks++) {
                int kk = ks * 8;
                unsigned a[4][4], b[4][2];
#pragma unroll
                for (int mt = 0; mt < 4; mt++) {
                    int row = wm + mt * 16;
                    a[mt][0] = __float_as_uint(Asb[(row + gid    ) * ASTR + kk + tidg]);
                    a[mt][1] = __float_as_uint(Asb[(row + gid + 8) * ASTR + kk + tidg]);
                    a[mt][2] = __float_as_uint(Asb[(row + gid    ) * ASTR + kk + tidg + 4]);
                    a[mt][3] = __float_as_uint(Asb[(row + gid + 8) * ASTR + kk + tidg + 4]);
                }
#pragma unroll
                for (int nt = 0; nt < 4; nt++) {
                    int col = wn + nt * 8;
                    b[nt][0] = __float_as_uint(Bsb[(col + gid) * ASTR + kk + tidg]);
                    b[nt][1] = __float_as_uint(Bsb[(col + gid) * ASTR + kk + tidg + 4]);
                }
#pragma unroll
                for (int mt = 0; mt < 4; mt++)
#pragma unroll
                    for (int nt = 0; nt < 4; nt++)
                        mma_tf32(c[mt][nt], a[mt], b[nt]);
            }
        }

#pragma unroll
        for (int mt = 0; mt < 4; mt++) {
#pragma unroll
            for (int nt = 0; nt < 4; nt++) {
                int col = bnl + wn + nt * 8 + 2 * tidg;
                float b0 = bv[col], b1 = bv[col + 1];
#pragma unroll
                for (int half = 0; half < 2; half++) {
                    int r = bm + wm + mt * 16 + gid + half * 8;
                    if (r < SEQ)
                        *(__half2*)(outv + (size_t)r * DIM + col) =
                            __floats2half2_rn(c[mt][nt][2*half] + b0, c[mt][nt][2*half+1] + b1);
                }
            }
        }
    }
}

// ============ WO GEMM: 64x128 tiles for full-wave occupancy ============
#define GA_STAGE (64 * ASTR)
#define WOSMEM ((2 * GA_STAGE + 2 * G_STAGE) * 4)     // 55296 B

__global__ __launch_bounds__(256) void wo_kernel(
    const float* __restrict__ A, const float* __restrict__ W,
    const float* __restrict__ bias, float* __restrict__ out)
{
    extern __shared__ __align__(16) char dyn[];
    float* smf = (float*)dyn;
    const int tid = threadIdx.x;
    const int bnl = blockIdx.x * 128, bm = blockIdx.y * 64;
    const int wid = tid >> 5, lane = tid & 31;
    const int wm = (wid & 1) * 32, wn = (wid >> 1) * 32;
    const int gid = lane >> 2, tidg = lane & 3;
    const unsigned sA = sptr(smf);
    const unsigned sB = sA + 2 * GA_STAGE * 4;
    const int lr = tid >> 3, lc = tid & 7;

    auto load_tile = [&](int st, int k0) {
#pragma unroll
        for (int l = 0; l < 2; l++) {                // A: 64 rows
            int r = lr + l * 32;
            unsigned off = (unsigned)(st * GA_STAGE + r * ASTR + lc * 4) * 4u;
            int gm = bm + r;
            int rowc = gm < SEQ ? gm : (SEQ - 1);
            cp16z(sA + off, A + (size_t)rowc * DIM + k0 + lc * 4, gm < SEQ ? 16 : 0);
        }
#pragma unroll
        for (int l = 0; l < 4; l++) {                // B: 128 rows
            int r = lr + l * 32;
            unsigned off = (unsigned)(st * G_STAGE + r * ASTR + lc * 4) * 4u;
            cp16(sB + off, W + (size_t)(bnl + r) * DIM + k0 + lc * 4);
        }
        cp_commit();
    };

    float c[2][4][4];
#pragma unroll
    for (int mt = 0; mt < 2; mt++)
#pragma unroll
        for (int nt = 0; nt < 4; nt++)
#pragma unroll
            for (int i = 0; i < 4; i++) c[mt][nt][i] = 0.f;

    load_tile(0, 0);
    for (int it = 0; it < NIT; it++) {
        cp_wait0();
        __syncthreads();
        if (it + 1 < NIT) load_tile((it + 1) & 1, (it + 1) * 32);

        const float* Asb = smf + (it & 1) * GA_STAGE;
        const float* Bsb = smf + 2 * GA_STAGE + (it & 1) * G_STAGE;
#pragma unroll
        for (int ks = 0; ks < 4; ks++) {
            int kk = ks * 8;
            unsigned a[2][4], b[4][2];
#pragma unroll
            for (int mt = 0; mt < 2; mt++) {
                int row = wm + mt * 16;
                a[mt][0] = __float_as_uint(Asb[(row + gid    ) * ASTR + kk + tidg]);
                a[mt][1] = __float_as_uint(Asb[(row + gid + 8) * ASTR + kk + tidg]);
                a[mt][2] = __float_as_uint(Asb[(row + gid    ) * ASTR + kk + tidg + 4]);
                a[mt][3] = __float_as_uint(Asb[(row + gid + 8) * ASTR + kk + tidg + 4]);
            }
#pragma unroll
            for (int nt = 0; nt < 4; nt++) {
                int col = wn + nt * 8;
                b[nt][0] = __float_as_uint(Bsb[(col + gid) * ASTR + kk + tidg]);
                b[nt][1] = __float_as_uint(Bsb[(col + gid) * ASTR + kk + tidg + 4]);
            }
#pragma unroll
            for (int mt = 0; mt < 2; mt++)
#pragma unroll
                for (int nt = 0; nt < 4; nt++)
                    mma_tf32(c[mt][nt], a[mt], b[nt]);
        }
    }

#pragma unroll
    for (int mt = 0; mt < 2; mt++) {
#pragma unroll
        for (int nt = 0; nt < 4; nt++) {
            int col = bnl + wn + nt * 8 + 2 * tidg;
            float b0 = bias[col], b1 = bias[col + 1];
#pragma unroll
            for (int half = 0; half < 2; half++) {
                int r = bm + wm + mt * 16 + gid + half * 8;
                if (r < SEQ)
                    *(float2*)(out + (size_t)r * DIM + col) =
                        make_float2(c[mt][nt][2*half] + b0, c[mt][nt][2*half+1] + b1);
            }
        }
    }
}

// -------------- fused RMSNorm + RoPE for q AND k --------
__global__ __launch_bounds__(256) void norm_rope2(
    const float* __restrict__ qin, const float* __restrict__ kin,
    const float* __restrict__ qw, const float* __restrict__ kw,
    const float* __restrict__ freqs,
    __half* __restrict__ qout, __half* __restrict__ kout, float qscale)
{
    const int s = blockIdx.x;
    const int which = blockIdx.y;
    const int tid = threadIdx.x;
    const float* row = (which ? kin : qin) + (size_t)s * DIM;
    const float* w   = which ? kw : qw;
    __half* out      = which ? kout : qout;
    const float outscale = which ? 1.0f : qscale;

    float ss = 0.f;
    for (int i = tid; i < DIM; i += 256) { float v = row[i]; ss += v * v; }
    __shared__ float red[8];
#pragma unroll
    for (int o = 16; o > 0; o >>= 1) ss += __shfl_xor_sync(0xffffffffu, ss, o);
    if ((tid & 31) == 0) red[tid >> 5] = ss;
    __syncthreads();
    if (tid < 32) {
        float v = (tid < 8) ? red[tid] : 0.f;
#pragma unroll
        for (int o = 4; o > 0; o >>= 1) v += __shfl_xor_sync(0xffffffffu, v, o);
        if (tid == 0) red[0] = v;
    }
    __syncthreads();
    const float scale = rsqrtf(red[0] / (float)DIM + 1e-6f);
    const int h_idx = s / W_DIM, w_idx = s % W_DIM;

    __half2* orow = (__half2*)(out + (size_t)s * DIM);
    for (int p = tid; p < DIM / 2; p += 256) {
        int j = p & 63;
        int ridx = (j < CF) ? GIDX : (j < CHW ? h_idx : w_idx);
        float cs = freqs[(ridx * 64 + j) * 2 + 0];
        float sn = freqs[(ridx * 64 + j) * 2 + 1];
        float x0 = row[2*p]   * scale * w[2*p];
        float x1 = row[2*p+1] * scale * w[2*p+1];
        orow[p] = __floats2half2_rn((x0 * cs - x1 * sn) * outscale,
                                    (x0 * sn + x1 * cs) * outscale);
    }
}

// ---- flash attention: split-KV x3, q64, 4 warps, single-sync pipeline -------
#define QSTR 136
#define BUF_B (64 * QSTR * 2)          // 17408 B per 64-row stage buffer
#define ATT_SMEM (4 * BUF_B)           // 69632 B: K0,K1,V0,V1; Q overlays K1
#define NKV_TILES (TOT_PAD / 64)       // 147

__global__ __launch_bounds__(128, 3) void attn_mma(
    const __half* __restrict__ Kh, const __half* __restrict__ Vh,
    const __half* __restrict__ Qh, float* __restrict__ Op, float* __restrict__ Lp)
{
    extern __shared__ __half smb[];
    const int h = blockIdx.y, q0 = blockIdx.x * 64;
    const int sp = blockIdx.z;
    const int it0 = sp * SPLIT_T;
    const int it1 = it0 + SPLIT_T;
    const bool has_tail = (it1 == NKV_TILES);
    const int tid = threadIdx.x, lane = tid & 31, wid = tid >> 5;
    const int gid = lane >> 2, tidg = lane & 3;

    const unsigned sK0 = sptr(smb);            // K stages at 0, BUF_B
    const unsigned sV0 = sK0 + 2 * BUF_B;      // V stages at 2,3 * BUF_B
    __half* Qs = smb + BUF_B / 2;              // Q overlays K stage 1
    const unsigned sQ = sK0 + BUF_B;

    const unsigned qoff = ((wid * 16 + (lane & 15)) * QSTR + (lane >> 4) * 8) * 2;
    const unsigned koff = (((lane >> 4) * 8 + (lane & 7)) * QSTR + ((lane >> 3) & 1) * 8) * 2;
    const unsigned voff = ((((lane >> 3) & 1) * 8 + (lane & 7)) * QSTR + (lane >> 4) * 8) * 2;

    // ---- load Q tile into overlay region (synchronous) ----
    {
        const int r = tid >> 1, cgb = (tid & 1) * 8;
#pragma unroll
        for (int i = 0; i < 8; i++) {
            int cg = cgb + i;
            *(uint4*)(Qs + r * QSTR + cg * 8) =
                *(const uint4*)(Qh + (size_t)(q0 + r) * DIM + h * HD + cg * 8);
        }
    }
    __syncthreads();                           // Q visible to all warps

    const int lr = tid >> 4, lc = tid & 15;
    auto load_kv = [&](int st, int t0) {
#pragma unroll
        for (int l = 0; l < 8; l++) {
            int r = lr + l * 8;
            unsigned off = (unsigned)(r * QSTR + lc * 8) * 2u + (unsigned)(st * BUF_B);
            const size_t g = (size_t)(t0 + r) * DIM + h * HD + lc * 8;
            cp16(sK0 + off, Kh + g);
            cp16(sV0 + off, Vh + g);
        }
        cp_commit();
    };

    load_kv(0, it0 * 64);                      // writes K0/V0 only (Q lives in K1)

    // ---- hoist Q fragments to registers (must precede K1's first write) ----
    unsigned qa[8][4];
#pragma unroll
    for (int j = 0; j < 8; j++)
        ldsm_x4(qa[j][0], qa[j][1], qa[j][2], qa[j][3], sQ + qoff + j * 32);
    __syncthreads();                           // all Q reads done before K1 overwrite

    float l0 = 0.f, l1 = 0.f;
    float o[16][4];
#pragma unroll
    for (int t = 0; t < 16; t++)
#pragma unroll
        for (int i = 0; i < 4; i++) o[t][i] = 0.f;

    for (int it = it0; it < it1; it++) {
        const int li = it - it0;

        // single-barrier pipeline: tile it is complete; everyone is done
        // consuming tile it-1, so prefetching it+1 into it-1's buffer is safe.
        cp_wait0();
        __syncthreads();
        if (it + 1 < it1) load_kv((li + 1) & 1, (it + 1) * 64);

        const unsigned kb = sK0 + (unsigned)((li & 1) * BUF_B) + koff;
        const unsigned vb = sV0 + (unsigned)((li & 1) * BUF_B) + voff;

        // ---- S = Q K^T ----
        float s[8][4];
#pragma unroll
        for (int nt = 0; nt < 8; nt++)
#pragma unroll
            for (int i = 0; i < 4; i++) s[nt][i] = 0.f;
#pragma unroll
        for (int ntp = 0; ntp < 4; ntp++) {
#pragma unroll
            for (int j = 0; j < 8; j++) {
                unsigned b0, b1, b2, b3;
                ldsm_x4(b0, b1, b2, b3, kb + (ntp * 16 * QSTR + j * 16) * 2);
                mma_f16(s[2*ntp],   qa[j][0], qa[j][1], qa[j][2], qa[j][3], b0, b1);
                mma_f16(s[2*ntp+1], qa[j][0], qa[j][1], qa[j][2], qa[j][3], b2, b3);
            }
        }

        // tail mask (pad keys are zeros -> would give P=1; mandatory)
        if (has_tail && it == NKV_TILES - 1) {
#pragma unroll
            for (int nt = 0; nt < 8; nt++) {
                int col = it * 64 + nt * 8 + 2 * tidg;
                if (col     >= TOTAL) { s[nt][0] = -1e4f; s[nt][2] = -1e4f; }
                if (col + 1 >= TOTAL) { s[nt][1] = -1e4f; s[nt][3] = -1e4f; }
            }
        }

        // ---- fixed-max softmax: P = exp2(s) ----
#pragma unroll
        for (int nt = 0; nt < 8; nt++) {
            s[nt][0] = ex2(s[nt][0]); s[nt][1] = ex2(s[nt][1]);
            s[nt][2] = ex2(s[nt][2]); s[nt][3] = ex2(s[nt][3]);
            l0 += s[nt][0] + s[nt][1];
            l1 += s[nt][2] + s[nt][3];
        }

        // ---- pack P fragments ----
        unsigned pa[4][4];
#pragma unroll
        for (int j = 0; j < 4; j++) {
            pa[j][0] = packh(s[2*j][0],   s[2*j][1]);
            pa[j][1] = packh(s[2*j][2],   s[2*j][3]);
            pa[j][2] = packh(s[2*j+1][0], s[2*j+1][1]);
            pa[j][3] = packh(s[2*j+1][2], s[2*j+1][3]);
        }

        // ---- O += P V ----
#pragma unroll
        for (int j = 0; j < 4; j++) {
#pragma unroll
            for (int dp = 0; dp < 8; dp++) {
                unsigned b0, b1, b2, b3;
                ldsm_x4t(b0, b1, b2, b3, vb + (j * 16 * QSTR + dp * 16) * 2);
                mma_f16(o[2*dp],   pa[j][0], pa[j][1], pa[j][2], pa[j][3], b0, b1);
                mma_f16(o[2*dp+1], pa[j][0], pa[j][1], pa[j][2], pa[j][3], b2, b3);
            }
        }
    }

    // ---- deferred quad reduction of row sums ----
    l0 += __shfl_xor_sync(0xffffffffu, l0, 1);
    l0 += __shfl_xor_sync(0xffffffffu, l0, 2);
    l1 += __shfl_xor_sync(0xffffffffu, l1, 1);
    l1 += __shfl_xor_sync(0xffffffffu, l1, 2);

    // ---- write UNNORMALIZED partial O and partial l ----
    float* Po = Op + (size_t)sp * SEQ_PAD * DIM;
    float* Pl = Lp + (size_t)sp * NH * SEQ_PAD + (size_t)h * SEQ_PAD;
    int r = q0 + wid * 16 + gid;
    if ((lane & 3) == 0) {
        if (r < SEQ)     Pl[r]     = l0;
        if (r + 8 < SEQ) Pl[r + 8] = l1;
    }
#pragma unroll
    for (int nt2 = 0; nt2 < 16; nt2++) {
        int col = h * HD + nt2 * 8 + 2 * tidg;
        if (r < SEQ)
            *(float2*)(Po + (size_t)r * DIM + col) = make_float2(o[nt2][0], o[nt2][1]);
        if (r + 8 < SEQ)
            *(float2*)(Po + (size_t)(r + 8) * DIM + col) = make_float2(o[nt2][2], o[nt2][3]);
    }
}

// ---- combine partials: attn = tf32((O0+O1+O2) / (l0+l1+l2)) ----
__global__ __launch_bounds__(256) void combine_kernel(
    const float* __restrict__ Op, const float* __restrict__ Lp,
    float* __restrict__ out)
{
    const int s = blockIdx.x;
    const int tid = threadIdx.x;
    const float* P0 = Op + (size_t)s * DIM;
    const float* P1 = Op + (size_t)SEQ_PAD * DIM + (size_t)s * DIM;
    const float* P2 = Op + (size_t)2 * SEQ_PAD * DIM + (size_t)s * DIM;

    __shared__ float invl[NH];
    if (tid < NH) {
        float l = Lp[tid * SEQ_PAD + s]
                + Lp[NH * SEQ_PAD + tid * SEQ_PAD + s]
                + Lp[2 * NH * SEQ_PAD + tid * SEQ_PAD + s];
        invl[tid] = 1.f / l;
    }
    __syncthreads();

    for (int i = tid; i < DIM / 4; i += 256) {
        float4 a = ((const float4*)P0)[i];
        float4 b = ((const float4*)P1)[i];
        float4 c = ((const float4*)P2)[i];
        float inv = invl[(i * 4) >> 7];
        float4 v = make_float4(
            __uint_as_float(f2tf32((a.x + b.x + c.x) * inv)),
            __uint_as_float(f2tf32((a.y + b.y + c.y) * inv)),
            __uint_as_float(f2tf32((a.z + b.z + c.z) * inv)),
            __uint_as_float(f2tf32((a.w + b.w + c.w) * inv)));
        ((float4*)(out + (size_t)s * DIM))[i] = v;
    }
}

// ------------------------------- host launcher -------------------------------
extern "C" void kernel_launch(void* const* d_in, const int* in_sizes, int n_in,
                              void* d_out, int out_size)
{
    const float* x     = (const float*)d_in[0];
    const float* wq    = (const float*)d_in[1];
    const float* bq    = (const float*)d_in[2];
    const float* wk    = (const float*)d_in[3];
    const float* bk    = (const float*)d_in[4];
    const float* wv    = (const float*)d_in[5];
    const float* bv    = (const float*)d_in[6];
    const float* wo    = (const float*)d_in[7];
    const float* bo    = (const float*)d_in[8];
    const float* nq_w  = (const float*)d_in[9];
    const float* nk_w  = (const float*)d_in[10];
    const float* freqs = (const float*)d_in[11];
    const float* kc    = (const float*)d_in[12];
    const float* vc    = (const float*)d_in[13];
    float* out = (float*)d_out;

    float *qp, *kp, *ap, *xr, *wvr, *wor, *po, *pl;
    __half *qh, *kh, *vh, *xh, *whq, *whk;
    cudaGetSymbolAddress((void**)&qp,  g_q);
    cudaGetSymbolAddress((void**)&kp,  g_k);
    cudaGetSymbolAddress((void**)&ap,  g_attn);
    cudaGetSymbolAddress((void**)&xr,  g_xr);
    cudaGetSymbolAddress((void**)&wvr, g_wvr);
    cudaGetSymbolAddress((void**)&wor, g_wor);
    cudaGetSymbolAddress((void**)&po,  g_po);
    cudaGetSymbolAddress((void**)&pl,  g_pl);
    cudaGetSymbolAddress((void**)&qh,  g_qh);
    cudaGetSymbolAddress((void**)&kh,  g_kh);
    cudaGetSymbolAddress((void**)&vh,  g_vh);
    cudaGetSymbolAddress((void**)&xh,  g_xh);
    cudaGetSymbolAddress((void**)&whq, g_whq);
    cudaGetSymbolAddress((void**)&whk, g_whk);

    cudaFuncSetAttribute(qkv_kernel, cudaFuncAttributeMaxDynamicSharedMemorySize, GSMEM);
    cudaFuncSetAttribute(wo_kernel,  cudaFuncAttributeMaxDynamicSharedMemorySize, WOSMEM);
    cudaFuncSetAttribute(attn_mma,   cudaFuncAttributeMaxDynamicSharedMemorySize, ATT_SMEM);

    prologue<<<1216, 256>>>(x, wq, wk, wv, wo, kc, vc);

    qkv_kernel<<<dim3(36, 13), 256, GSMEM>>>(
        xh, whq, whk, xr, wvr, bq, bk, bv,
        qp, kp, vh + (size_t)START * DIM);

    const float qscale = 0.08838834764831845f * 1.4426950408889634f;  // 1/sqrt(d)*log2(e)
    norm_rope2<<<dim3(SEQ, 2), 256>>>(qp, kp, nq_w, nk_w, freqs,
                                      qh, kh + (size_t)START * DIM, qscale);

    attn_mma<<<dim3(SEQ_PAD / 64, NH, NSPLIT), 128, ATT_SMEM>>>(kh, vh, qh, po, pl);

    combine_kernel<<<SEQ, 256>>>(po, pl, ap);

    wo_kernel<<<dim3(12, 25), 256, WOSMEM>>>(ap, wor, bo, out);
}

// round 17
// speedup vs baseline: 1.0034x; 1.0034x over previous
#include <cuda_runtime.h>
#include <cuda_fp16.h>
#include <math.h>

#define SEQ     1560
#define SEQ_PAD 1600
#define DIM     1536
#define NH      12
#define HD      128
#define TOTAL   9360
#define TOT_PAD 9408
#define START   7800
#define W_DIM   52
#define GIDX    5
#define CF      22
#define CHW     43

#define NSPLIT  3
#define SPLIT_T 49                 // 147 tiles = 3 x 49

// ---------------- scratch (no allocations allowed) ----------------
__device__ __align__(16) float  g_q[SEQ * DIM];
__device__ __align__(16) float  g_k[SEQ * DIM];
__device__ __align__(16) float  g_attn[SEQ * DIM];
__device__ __align__(16) float  g_xr[SEQ * DIM];
__device__ __align__(16) float  g_wvr[DIM * DIM];
__device__ __align__(16) float  g_wor[DIM * DIM];
__device__ __align__(16) float  g_po[NSPLIT * SEQ_PAD * DIM];   // partial O
__device__ __align__(16) float  g_pl[NSPLIT * NH * SEQ_PAD];    // partial l
__device__ __align__(16) __half g_xh[SEQ * DIM];
__device__ __align__(16) __half g_whq[DIM * DIM];
__device__ __align__(16) __half g_whk[DIM * DIM];
__device__ __align__(16) __half g_qh[SEQ_PAD * DIM];
__device__ __align__(16) __half g_kh[TOT_PAD * DIM];
__device__ __align__(16) __half g_vh[TOT_PAD * DIM];

// ---------------- asm helpers ----------------
__device__ __forceinline__ unsigned f2tf32(float f) {
    unsigned r; asm("cvt.rna.tf32.f32 %0, %1;" : "=r"(r) : "f"(f)); return r;
}
__device__ __forceinline__ float ex2(float x) {
    float r; asm("ex2.approx.ftz.f32 %0, %1;" : "=f"(r) : "f"(x)); return r;
}
__device__ __forceinline__ unsigned packh(float lo, float hi) {
    __half2 h = __floats2half2_rn(lo, hi);
    return *(unsigned*)&h;
}
__device__ __forceinline__ unsigned sptr(const void* p) {
    return (unsigned)__cvta_generic_to_shared(p);
}
__device__ __forceinline__ void cp16(unsigned dst, const void* src) {
    asm volatile("cp.async.cg.shared.global [%0], [%1], 16;" :: "r"(dst), "l"(src));
}
__device__ __forceinline__ void cp16z(unsigned dst, const void* src, int sz) {
    asm volatile("cp.async.cg.shared.global [%0], [%1], 16, %2;" :: "r"(dst), "l"(src), "r"(sz));
}
__device__ __forceinline__ void cp_commit() { asm volatile("cp.async.commit_group;"); }
__device__ __forceinline__ void cp_wait0() { asm volatile("cp.async.wait_group 0;"); }
__device__ __forceinline__ void ldsm_x4(unsigned& r0, unsigned& r1, unsigned& r2, unsigned& r3, unsigned a) {
    asm volatile("ldmatrix.sync.aligned.m8n8.x4.shared.b16 {%0,%1,%2,%3}, [%4];"
                 : "=r"(r0), "=r"(r1), "=r"(r2), "=r"(r3) : "r"(a));
}
__device__ __forceinline__ void ldsm_x4t(unsigned& r0, unsigned& r1, unsigned& r2, unsigned& r3, unsigned a) {
    asm volatile("ldmatrix.sync.aligned.m8n8.x4.trans.shared.b16 {%0,%1,%2,%3}, [%4];"
                 : "=r"(r0), "=r"(r1), "=r"(r2), "=r"(r3) : "r"(a));
}
__device__ __forceinline__ void mma_tf32(float* c, const unsigned* a, const unsigned* b) {
    asm volatile("mma.sync.aligned.m16n8k8.row.col.f32.tf32.tf32.f32 "
                 "{%0,%1,%2,%3}, {%4,%5,%6,%7}, {%8,%9}, {%0,%1,%2,%3};\n"
                 : "+f"(c[0]), "+f"(c[1]), "+f"(c[2]), "+f"(c[3])
                 : "r"(a[0]), "r"(a[1]), "r"(a[2]), "r"(a[3]), "r"(b[0]), "r"(b[1]));
}
__device__ __forceinline__ void mma_f16(float* c, unsigned a0, unsigned a1,
                                        unsigned a2, unsigned a3,
                                        unsigned b0, unsigned b1) {
    asm volatile("mma.sync.aligned.m16n8k16.row.col.f32.f16.f16.f32 "
                 "{%0,%1,%2,%3}, {%4,%5,%6,%7}, {%8,%9}, {%0,%1,%2,%3};\n"
                 : "+f"(c[0]), "+f"(c[1]), "+f"(c[2]), "+f"(c[3])
                 : "r"(a0), "r"(a1), "r"(a2), "r"(a3), "r"(b0), "r"(b1));
}

// ======================= fused prologue =======================
__global__ __launch_bounds__(256) void prologue(
    const float* __restrict__ x,
    const float* __restrict__ wq, const float* __restrict__ wk,
    const float* __restrict__ wv, const float* __restrict__ wo,
    const float* __restrict__ kc, const float* __restrict__ vc)
{
    const int g = blockIdx.x * 256 + threadIdx.x;
    const int stride = gridDim.x * 256;

    const int WN4 = DIM * DIM / 4;
    const int XN4 = SEQ * DIM / 4;
    const int KN4 = START * DIM / 4;

    for (int i = g; i < WN4; i += stride) {
        float4 a = ((const float4*)wv)[i];
        float4 b = ((const float4*)wo)[i];
        a.x = __uint_as_float(f2tf32(a.x)); a.y = __uint_as_float(f2tf32(a.y));
        a.z = __uint_as_float(f2tf32(a.z)); a.w = __uint_as_float(f2tf32(a.w));
        b.x = __uint_as_float(f2tf32(b.x)); b.y = __uint_as_float(f2tf32(b.y));
        b.z = __uint_as_float(f2tf32(b.z)); b.w = __uint_as_float(f2tf32(b.w));
        ((float4*)g_wvr)[i] = a;
        ((float4*)g_wor)[i] = b;
    }
    for (int i = g; i < XN4; i += stride) {
        float4 v = ((const float4*)x)[i];
        float4 r = make_float4(__uint_as_float(f2tf32(v.x)), __uint_as_float(f2tf32(v.y)),
                               __uint_as_float(f2tf32(v.z)), __uint_as_float(f2tf32(v.w)));
        ((float4*)g_xr)[i] = r;
        ((__half2*)g_xh)[2*i]   = __floats2half2_rn(v.x, v.y);
        ((__half2*)g_xh)[2*i+1] = __floats2half2_rn(v.z, v.w);
    }
    for (int i = g; i < WN4; i += stride) {
        float4 a = ((const float4*)wq)[i];
        float4 b = ((const float4*)wk)[i];
        ((__half2*)g_whq)[2*i]   = __floats2half2_rn(a.x, a.y);
        ((__half2*)g_whq)[2*i+1] = __floats2half2_rn(a.z, a.w);
        ((__half2*)g_whk)[2*i]   = __floats2half2_rn(b.x, b.y);
        ((__half2*)g_whk)[2*i+1] = __floats2half2_rn(b.z, b.w);
    }
    for (int i = g; i < KN4; i += stride) {
        float4 a = ((const float4*)kc)[i];
        float4 b = ((const float4*)vc)[i];
        ((__half2*)g_kh)[2*i]   = __floats2half2_rn(a.x, a.y);
        ((__half2*)g_kh)[2*i+1] = __floats2half2_rn(a.z, a.w);
        ((__half2*)g_vh)[2*i]   = __floats2half2_rn(b.x, b.y);
        ((__half2*)g_vh)[2*i+1] = __floats2half2_rn(b.z, b.w);
    }
    const int NQP = (SEQ_PAD - SEQ) * DIM / 8;
    const int NKP = (TOT_PAD - TOTAL) * DIM / 8;
    const uint4 z = make_uint4(0, 0, 0, 0);
    for (int i = g; i < NQP; i += stride) ((uint4*)(g_qh + (size_t)SEQ * DIM))[i] = z;
    for (int i = g; i < NKP; i += stride) {
        ((uint4*)(g_kh + (size_t)TOTAL * DIM))[i] = z;
        ((uint4*)(g_vh + (size_t)TOTAL * DIM))[i] = z;
    }
}

// ================= fused QKV GEMM (mixed fp16 / tf32) =================
// LPT ordering: bx<12 = tf32 V tiles (LONG jobs, launched first),
//               bx>=12 = fp16 Q/K tiles (short jobs).
#define ASTR 36
#define G_STAGE (128 * ASTR)
#define GSMEM (4 * G_STAGE * 4)
#define HSTR 40
#define H_STAGE (128 * HSTR)
#define NIT (DIM / 32)

__global__ __launch_bounds__(256) void qkv_kernel(
    const __half* __restrict__ xh,
    const __half* __restrict__ whq, const __half* __restrict__ whk,
    const float* __restrict__ xr, const float* __restrict__ wvr,
    const float* __restrict__ bq, const float* __restrict__ bk, const float* __restrict__ bv,
    float* __restrict__ outq, float* __restrict__ outk, __half* __restrict__ outv)
{
    extern __shared__ __align__(16) char dyn[];
    const int tid = threadIdx.x;
    const int bm = blockIdx.y * 128;
    const int wid = tid >> 5, lane = tid & 31;
    const int wm = (wid & 1) * 64, wn = (wid >> 1) * 32;
    const int gid = lane >> 2, tidg = lane & 3;

    float c[4][4][4];
#pragma unroll
    for (int mt = 0; mt < 4; mt++)
#pragma unroll
        for (int nt = 0; nt < 4; nt++)
#pragma unroll
            for (int i = 0; i < 4; i++) c[mt][nt][i] = 0.f;

    if (blockIdx.x >= 12) {
        // ---------------- fp16 Q/K path (short jobs, launched after V) -------
        const int bxf = blockIdx.x - 12;
        const int sec = bxf / 12;
        const int bnl = (bxf % 12) * 128;
        const __half* W    = sec ? whk : whq;
        const float* bias  = sec ? bk : bq;
        float* outp        = sec ? outk : outq;

        __half* smh = (__half*)dyn;
        const unsigned sA = sptr(smh);
        const unsigned sB = sA + 2 * H_STAGE * 2;

        auto load_tile = [&](int st, int k0) {
#pragma unroll
            for (int l = 0; l < 2; l++) {
                int idx = tid + 256 * l;
                int r = idx >> 2, ch = idx & 3;
                unsigned off = (unsigned)(st * H_STAGE + r * HSTR + ch * 8) * 2u;
                int gm = bm + r;
                int rowc = gm < SEQ ? gm : (SEQ - 1);
                cp16z(sA + off, xh + (size_t)rowc * DIM + k0 + ch * 8, gm < SEQ ? 16 : 0);
                cp16 (sB + off, W  + (size_t)(bnl + r) * DIM + k0 + ch * 8);
            }
            cp_commit();
        };

        const unsigned aoff = ((lane & 15) * HSTR + (lane >> 4) * 8) * 2;
        const unsigned boff = (((lane >> 4) * 8 + (lane & 7)) * HSTR + ((lane >> 3) & 1) * 8) * 2;

        load_tile(0, 0);
        for (int it = 0; it < NIT; it++) {
            cp_wait0();
            __syncthreads();
            if (it + 1 < NIT) load_tile((it + 1) & 1, (it + 1) * 32);

            const unsigned aB = sA + (unsigned)((it & 1) * H_STAGE * 2);
            const unsigned bB = sB + (unsigned)((it & 1) * H_STAGE * 2);
#pragma unroll
            for (int kf = 0; kf < 2; kf++) {
                unsigned a[4][4];
#pragma unroll
                for (int mt = 0; mt < 4; mt++)
                    ldsm_x4(a[mt][0], a[mt][1], a[mt][2], a[mt][3],
                            aB + (unsigned)(((wm + mt * 16) * HSTR + kf * 16) * 2) + aoff);
#pragma unroll
                for (int np = 0; np < 2; np++) {
                    unsigned b0, b1, b2, b3;
                    ldsm_x4(b0, b1, b2, b3,
                            bB + (unsigned)(((wn + np * 16) * HSTR + kf * 16) * 2) + boff);
#pragma unroll
                    for (int mt = 0; mt < 4; mt++) {
                        mma_f16(c[mt][2*np],   a[mt][0], a[mt][1], a[mt][2], a[mt][3], b0, b1);
                        mma_f16(c[mt][2*np+1], a[mt][0], a[mt][1], a[mt][2], a[mt][3], b2, b3);
                    }
                }
            }
        }

#pragma unroll
        for (int mt = 0; mt < 4; mt++) {
#pragma unroll
            for (int nt = 0; nt < 4; nt++) {
                int col = bnl + wn + nt * 8 + 2 * tidg;
                float b0 = bias[col], b1 = bias[col + 1];
#pragma unroll
                for (int half = 0; half < 2; half++) {
                    int r = bm + wm + mt * 16 + gid + half * 8;
                    if (r < SEQ)
                        *(float2*)(outp + (size_t)r * DIM + col) =
                            make_float2(c[mt][nt][2*half] + b0, c[mt][nt][2*half+1] + b1);
                }
            }
        }
    } else {
        // ---------------- tf32 V path (long jobs, launched FIRST) ------------
        const int bnl = blockIdx.x * 128;
        float* smf = (float*)dyn;
        const unsigned sA = sptr(smf);
        const unsigned sB = sA + 2 * G_STAGE * 4;
        const int lr = tid >> 3, lc = tid & 7;

        auto load_tile = [&](int st, int k0) {
#pragma unroll
            for (int l = 0; l < 4; l++) {
                int r = lr + l * 32;
                unsigned off = (unsigned)(st * G_STAGE + r * ASTR + lc * 4) * 4u;
                int gm = bm + r;
                int rowc = gm < SEQ ? gm : (SEQ - 1);
                cp16z(sA + off, xr + (size_t)rowc * DIM + k0 + lc * 4, gm < SEQ ? 16 : 0);
                cp16 (sB + off, wvr + (size_t)(bnl + r) * DIM + k0 + lc * 4);
            }
            cp_commit();
        };

        load_tile(0, 0);
        for (int it = 0; it < NIT; it++) {
            cp_wait0();
            __syncthreads();
            if (it + 1 < NIT) load_tile((it + 1) & 1, (it + 1) * 32);

            const float* Asb = smf + (it & 1) * G_STAGE;
            const float* Bsb = smf + 2 * G_STAGE + (it & 1) * G_STAGE;
#pragma unroll
            for (int ks = 0; ks < 4; ks++) {
                int kk = ks * 8;
                unsigned a[4][4], b[4][2];
#pragma unroll
                for (int mt = 0; mt < 4; mt++) {
                    int row = wm + mt * 16;
                    a[mt][0] = __float_as_uint(Asb[(row + gid    ) * ASTR + kk + tidg]);
                    a[mt][1] = __float_as_uint(Asb[(row + gid + 8) * ASTR + kk + tidg]);
                    a[mt][2] = __float_as_uint(Asb[(row + gid    ) * ASTR + kk + tidg + 4]);
                    a[mt][3] = __float_as_uint(Asb[(row + gid + 8) * ASTR + kk + tidg + 4]);
                }
#pragma unroll
                for (int nt = 0; nt < 4; nt++) {
                    int col = wn + nt * 8;
                    b[nt][0] = __float_as_uint(Bsb[(col + gid) * ASTR + kk + tidg]);
                    b[nt][1] = __float_as_uint(Bsb[(col + gid) * ASTR + kk + tidg + 4]);
                }
#pragma unroll
                for (int mt = 0; mt < 4; mt++)
#pragma unroll
                    for (int nt = 0; nt < 4; nt++)
                        mma_tf32(c[mt][nt], a[mt], b[nt]);
            }
        }

#pragma unroll
        for (int mt = 0; mt < 4; mt++) {
#pragma unroll
            for (int nt = 0; nt < 4; nt++) {
                int col = bnl + wn + nt * 8 + 2 * tidg;
                float b0 = bv[col], b1 = bv[col + 1];
#pragma unroll
                for (int half = 0; half < 2; half++) {
                    int r = bm + wm + mt * 16 + gid + half * 8;
                    if (r < SEQ)
                        *(__half2*)(outv + (size_t)r * DIM + col) =
                            __floats2half2_rn(c[mt][nt][2*half] + b0, c[mt][nt][2*half+1] + b1);
                }
            }
        }
    }
}

// ============ WO GEMM: 64x128 tiles for full-wave occupancy ============
#define GA_STAGE (64 * ASTR)
#define WOSMEM ((2 * GA_STAGE + 2 * G_STAGE) * 4)     // 55296 B

__global__ __launch_bounds__(256) void wo_kernel(
    const float* __restrict__ A, const float* __restrict__ W,
    const float* __restrict__ bias, float* __restrict__ out)
{
    extern __shared__ __align__(16) char dyn[];
    float* smf = (float*)dyn;
    const int tid = threadIdx.x;
    const int bnl = blockIdx.x * 128, bm = blockIdx.y * 64;
    const int wid = tid >> 5, lane = tid & 31;
    const int wm = (wid & 1) * 32, wn = (wid >> 1) * 32;
    const int gid = lane >> 2, tidg = lane & 3;
    const unsigned sA = sptr(smf);
    const unsigned sB = sA + 2 * GA_STAGE * 4;
    const int lr = tid >> 3, lc = tid & 7;

    auto load_tile = [&](int st, int k0) {
#pragma unroll
        for (int l = 0; l < 2; l++) {                // A: 64 rows
            int r = lr + l * 32;
            unsigned off = (unsigned)(st * GA_STAGE + r * ASTR + lc * 4) * 4u;
            int gm = bm + r;
            int rowc = gm < SEQ ? gm : (SEQ - 1);
            cp16z(sA + off, A + (size_t)rowc * DIM + k0 + lc * 4, gm < SEQ ? 16 : 0);
        }
#pragma unroll
        for (int l = 0; l < 4; l++) {                // B: 128 rows
            int r = lr + l * 32;
            unsigned off = (unsigned)(st * G_STAGE + r * ASTR + lc * 4) * 4u;
            cp16(sB + off, W + (size_t)(bnl + r) * DIM + k0 + lc * 4);
        }
        cp_commit();
    };

    float c[2][4][4];
#pragma unroll
    for (int mt = 0; mt < 2; mt++)
#pragma unroll
        for (int nt = 0; nt < 4; nt++)
#pragma unroll
            for (int i = 0; i < 4; i++) c[mt][nt][i] = 0.f;

    load_tile(0, 0);
    for (int it = 0; it < NIT; it++) {
        cp_wait0();
        __syncthreads();
        if (it + 1 < NIT) load_tile((it + 1) & 1, (it + 1) * 32);

        const float* Asb = smf + (it & 1) * GA_STAGE;
        const float* Bsb = smf + 2 * GA_STAGE + (it & 1) * G_STAGE;
#pragma unroll
        for (int ks = 0; ks < 4; ks++) {
            int kk = ks * 8;
            unsigned a[2][4], b[4][2];
#pragma unroll
            for (int mt = 0; mt < 2; mt++) {
                int row = wm + mt * 16;
                a[mt][0] = __float_as_uint(Asb[(row + gid    ) * ASTR + kk + tidg]);
                a[mt][1] = __float_as_uint(Asb[(row + gid + 8) * ASTR + kk + tidg]);
                a[mt][2] = __float_as_uint(Asb[(row + gid    ) * ASTR + kk + tidg + 4]);
                a[mt][3] = __float_as_uint(Asb[(row + gid + 8) * ASTR + kk + tidg + 4]);
            }
#pragma unroll
            for (int nt = 0; nt < 4; nt++) {
                int col = wn + nt * 8;
                b[nt][0] = __float_as_uint(Bsb[(col + gid) * ASTR + kk + tidg]);
                b[nt][1] = __float_as_uint(Bsb[(col + gid) * ASTR + kk + tidg + 4]);
            }
#pragma unroll
            for (int mt = 0; mt < 2; mt++)
#pragma unroll
                for (int nt = 0; nt < 4; nt++)
                    mma_tf32(c[mt][nt], a[mt], b[nt]);
        }
    }

#pragma unroll
    for (int mt = 0; mt < 2; mt++) {
#pragma unroll
        for (int nt = 0; nt < 4; nt++) {
            int col = bnl + wn + nt * 8 + 2 * tidg;
            float b0 = bias[col], b1 = bias[col + 1];
#pragma unroll
            for (int half = 0; half < 2; half++) {
                int r = bm + wm + mt * 16 + gid + half * 8;
                if (r < SEQ)
                    *(float2*)(out + (size_t)r * DIM + col) =
                        make_float2(c[mt][nt][2*half] + b0, c[mt][nt][2*half+1] + b1);
            }
        }
    }
}

// -------------- fused RMSNorm + RoPE for q AND k --------
__global__ __launch_bounds__(256) void norm_rope2(
    const float* __restrict__ qin, const float* __restrict__ kin,
    const float* __restrict__ qw, const float* __restrict__ kw,
    const float* __restrict__ freqs,
    __half* __restrict__ qout, __half* __restrict__ kout, float qscale)
{
    const int s = blockIdx.x;
    const int which = blockIdx.y;
    const int tid = threadIdx.x;
    const float* row = (which ? kin : qin) + (size_t)s * DIM;
    const float* w   = which ? kw : qw;
    __half* out      = which ? kout : qout;
    const float outscale = which ? 1.0f : qscale;

    float ss = 0.f;
    for (int i = tid; i < DIM; i += 256) { float v = row[i]; ss += v * v; }
    __shared__ float red[8];
#pragma unroll
    for (int o = 16; o > 0; o >>= 1) ss += __shfl_xor_sync(0xffffffffu, ss, o);
    if ((tid & 31) == 0) red[tid >> 5] = ss;
    __syncthreads();
    if (tid < 32) {
        float v = (tid < 8) ? red[tid] : 0.f;
#pragma unroll
        for (int o = 4; o > 0; o >>= 1) v += __shfl_xor_sync(0xffffffffu, v, o);
        if (tid == 0) red[0] = v;
    }
    __syncthreads();
    const float scale = rsqrtf(red[0] / (float)DIM + 1e-6f);
    const int h_idx = s / W_DIM, w_idx = s % W_DIM;

    __half2* orow = (__half2*)(out + (size_t)s * DIM);
    for (int p = tid; p < DIM / 2; p += 256) {
        int j = p & 63;
        int ridx = (j < CF) ? GIDX : (j < CHW ? h_idx : w_idx);
        float cs = freqs[(ridx * 64 + j) * 2 + 0];
        float sn = freqs[(ridx * 64 + j) * 2 + 1];
        float x0 = row[2*p]   * scale * w[2*p];
        float x1 = row[2*p+1] * scale * w[2*p+1];
        orow[p] = __floats2half2_rn((x0 * cs - x1 * sn) * outscale,
                                    (x0 * sn + x1 * cs) * outscale);
    }
}

// ---- flash attention: split-KV x3, q64, 4 warps, single-sync pipeline -------
#define QSTR 136
#define BUF_B (64 * QSTR * 2)          // 17408 B per 64-row stage buffer
#define ATT_SMEM (4 * BUF_B)           // 69632 B: K0,K1,V0,V1; Q overlays K1
#define NKV_TILES (TOT_PAD / 64)       // 147

__global__ __launch_bounds__(128, 3) void attn_mma(
    const __half* __restrict__ Kh, const __half* __restrict__ Vh,
    const __half* __restrict__ Qh, float* __restrict__ Op, float* __restrict__ Lp)
{
    extern __shared__ __half smb[];
    const int h = blockIdx.y, q0 = blockIdx.x * 64;
    const int sp = blockIdx.z;
    const int it0 = sp * SPLIT_T;
    const int it1 = it0 + SPLIT_T;
    const bool has_tail = (it1 == NKV_TILES);
    const int tid = threadIdx.x, lane = tid & 31, wid = tid >> 5;
    const int gid = lane >> 2, tidg = lane & 3;

    const unsigned sK0 = sptr(smb);            // K stages at 0, BUF_B
    const unsigned sV0 = sK0 + 2 * BUF_B;      // V stages at 2,3 * BUF_B
    __half* Qs = smb + BUF_B / 2;              // Q overlays K stage 1
    const unsigned sQ = sK0 + BUF_B;

    const unsigned qoff = ((wid * 16 + (lane & 15)) * QSTR + (lane >> 4) * 8) * 2;
    const unsigned koff = (((lane >> 4) * 8 + (lane & 7)) * QSTR + ((lane >> 3) & 1) * 8) * 2;
    const unsigned voff = ((((lane >> 3) & 1) * 8 + (lane & 7)) * QSTR + (lane >> 4) * 8) * 2;

    // ---- load Q tile into overlay region (synchronous) ----
    {
        const int r = tid >> 1, cgb = (tid & 1) * 8;
#pragma unroll
        for (int i = 0; i < 8; i++) {
            int cg = cgb + i;
            *(uint4*)(Qs + r * QSTR + cg * 8) =
                *(const uint4*)(Qh + (size_t)(q0 + r) * DIM + h * HD + cg * 8);
        }
    }
    __syncthreads();                           // Q visible to all warps

    const int lr = tid >> 4, lc = tid & 15;
    auto load_kv = [&](int st, int t0) {
#pragma unroll
        for (int l = 0; l < 8; l++) {
            int r = lr + l * 8;
            unsigned off = (unsigned)(r * QSTR + lc * 8) * 2u + (unsigned)(st * BUF_B);
            const size_t g = (size_t)(t0 + r) * DIM + h * HD + lc * 8;
            cp16(sK0 + off, Kh + g);
            cp16(sV0 + off, Vh + g);
        }
        cp_commit();
    };

    load_kv(0, it0 * 64);                      // writes K0/V0 only (Q lives in K1)

    // ---- hoist Q fragments to registers (must precede K1's first write) ----
    unsigned qa[8][4];
#pragma unroll
    for (int j = 0; j < 8; j++)
        ldsm_x4(qa[j][0], qa[j][1], qa[j][2], qa[j][3], sQ + qoff + j * 32);
    __syncthreads();                           // all Q reads done before K1 overwrite

    float l0 = 0.f, l1 = 0.f;
    float o[16][4];
#pragma unroll
    for (int t = 0; t < 16; t++)
#pragma unroll
        for (int i = 0; i < 4; i++) o[t][i] = 0.f;

    for (int it = it0; it < it1; it++) {
        const int li = it - it0;

        // single-barrier pipeline: tile it is complete; everyone is done
        // consuming tile it-1, so prefetching it+1 into it-1's buffer is safe.
        cp_wait0();
        __syncthreads();
        if (it + 1 < it1) load_kv((li + 1) & 1, (it + 1) * 64);

        const unsigned kb = sK0 + (unsigned)((li & 1) * BUF_B) + koff;
        const unsigned vb = sV0 + (unsigned)((li & 1) * BUF_B) + voff;

        // ---- S = Q K^T ----
        float s[8][4];
#pragma unroll
        for (int nt = 0; nt < 8; nt++)
#pragma unroll
            for (int i = 0; i < 4; i++) s[nt][i] = 0.f;
#pragma unroll
        for (int ntp = 0; ntp < 4; ntp++) {
#pragma unroll
            for (int j = 0; j < 8; j++) {
                unsigned b0, b1, b2, b3;
                ldsm_x4(b0, b1, b2, b3, kb + (ntp * 16 * QSTR + j * 16) * 2);
                mma_f16(s[2*ntp],   qa[j][0], qa[j][1], qa[j][2], qa[j][3], b0, b1);
                mma_f16(s[2*ntp+1], qa[j][0], qa[j][1], qa[j][2], qa[j][3], b2, b3);
            }
        }

        // tail mask (pad keys are zeros -> would give P=1; mandatory)
        if (has_tail && it == NKV_TILES - 1) {
#pragma unroll
            for (int nt = 0; nt < 8; nt++) {
                int col = it * 64 + nt * 8 + 2 * tidg;
                if (col     >= TOTAL) { s[nt][0] = -1e4f; s[nt][2] = -1e4f; }
                if (col + 1 >= TOTAL) { s[nt][1] = -1e4f; s[nt][3] = -1e4f; }
            }
        }

        // ---- fixed-max softmax: P = exp2(s) ----
#pragma unroll
        for (int nt = 0; nt < 8; nt++) {
            s[nt][0] = ex2(s[nt][0]); s[nt][1] = ex2(s[nt][1]);
            s[nt][2] = ex2(s[nt][2]); s[nt][3] = ex2(s[nt][3]);
            l0 += s[nt][0] + s[nt][1];
            l1 += s[nt][2] + s[nt][3];
        }

        // ---- pack P fragments ----
        unsigned pa[4][4];
#pragma unroll
        for (int j = 0; j < 4; j++) {
            pa[j][0] = packh(s[2*j][0],   s[2*j][1]);
            pa[j][1] = packh(s[2*j][2],   s[2*j][3]);
            pa[j][2] = packh(s[2*j+1][0], s[2*j+1][1]);
            pa[j][3] = packh(s[2*j+1][2], s[2*j+1][3]);
        }

        // ---- O += P V ----
#pragma unroll
        for (int j = 0; j < 4; j++) {
#pragma unroll
            for (int dp = 0; dp < 8; dp++) {
                unsigned b0, b1, b2, b3;
                ldsm_x4t(b0, b1, b2, b3, vb + (j * 16 * QSTR + dp * 16) * 2);
                mma_f16(o[2*dp],   pa[j][0], pa[j][1], pa[j][2], pa[j][3], b0, b1);
                mma_f16(o[2*dp+1], pa[j][0], pa[j][1], pa[j][2], pa[j][3], b2, b3);
            }
        }
    }

    // ---- deferred quad reduction of row sums ----
    l0 += __shfl_xor_sync(0xffffffffu, l0, 1);
    l0 += __shfl_xor_sync(0xffffffffu, l0, 2);
    l1 += __shfl_xor_sync(0xffffffffu, l1, 1);
    l1 += __shfl_xor_sync(0xffffffffu, l1, 2);

    // ---- write UNNORMALIZED partial O and partial l ----
    float* Po = Op + (size_t)sp * SEQ_PAD * DIM;
    float* Pl = Lp + (size_t)sp * NH * SEQ_PAD + (size_t)h * SEQ_PAD;
    int r = q0 + wid * 16 + gid;
    if ((lane & 3) == 0) {
        if (r < SEQ)     Pl[r]     = l0;
        if (r + 8 < SEQ) Pl[r + 8] = l1;
    }
#pragma unroll
    for (int nt2 = 0; nt2 < 16; nt2++) {
        int col = h * HD + nt2 * 8 + 2 * tidg;
        if (r < SEQ)
            *(float2*)(Po + (size_t)r * DIM + col) = make_float2(o[nt2][0], o[nt2][1]);
        if (r + 8 < SEQ)
            *(float2*)(Po + (size_t)(r + 8) * DIM + col) = make_float2(o[nt2][2], o[nt2][3]);
    }
}

// ---- combine partials: attn = tf32((O0+O1+O2) / (l0+l1+l2)) ----
__global__ __launch_bounds__(256) void combine_kernel(
    const float* __restrict__ Op, const float* __restrict__ Lp,
    float* __restrict__ out)
{
    const int s = blockIdx.x;
    const int tid = threadIdx.x;
    const float* P0 = Op + (size_t)s * DIM;
    const float* P1 = Op + (size_t)SEQ_PAD * DIM + (size_t)s * DIM;
    const float* P2 = Op + (size_t)2 * SEQ_PAD * DIM + (size_t)s * DIM;

    __shared__ float invl[NH];
    if (tid < NH) {
        float l = Lp[tid * SEQ_PAD + s]
                + Lp[NH * SEQ_PAD + tid * SEQ_PAD + s]
                + Lp[2 * NH * SEQ_PAD + tid * SEQ_PAD + s];
        invl[tid] = 1.f / l;
    }
    __syncthreads();

    for (int i = tid; i < DIM / 4; i += 256) {
        float4 a = ((const float4*)P0)[i];
        float4 b = ((const float4*)P1)[i];
        float4 c = ((const float4*)P2)[i];
        float inv = invl[(i * 4) >> 7];
        float4 v = make_float4(
            __uint_as_float(f2tf32((a.x + b.x + c.x) * inv)),
            __uint_as_float(f2tf32((a.y + b.y + c.y) * inv)),
            __uint_as_float(f2tf32((a.z + b.z + c.z) * inv)),
            __uint_as_float(f2tf32((a.w + b.w + c.w) * inv)));
        ((float4*)(out + (size_t)s * DIM))[i] = v;
    }
}

// ------------------------------- host launcher -------------------------------
extern "C" void kernel_launch(void* const* d_in, const int* in_sizes, int n_in,
                              void* d_out, int out_size)
{
    const float* x     = (const float*)d_in[0];
    const float* wq    = (const float*)d_in[1];
    const float* bq    = (const float*)d_in[2];
    const float* wk    = (const float*)d_in[3];
    const float* bk    = (const float*)d_in[4];
    const float* wv    = (const float*)d_in[5];
    const float* bv    = (const float*)d_in[6];
    const float* wo    = (const float*)d_in[7];
    const float* bo    = (const float*)d_in[8];
    const float* nq_w  = (const float*)d_in[9];
    const float* nk_w  = (const float*)d_in[10];
    const float* freqs = (const float*)d_in[11];
    const float* kc    = (const float*)d_in[12];
    const float* vc    = (const float*)d_in[13];
    float* out = (float*)d_out;

    float *qp, *kp, *ap, *xr, *wvr, *wor, *po, *pl;
    __half *qh, *kh, *vh, *xh, *whq, *whk;
    cudaGetSymbolAddress((void**)&qp,  g_q);
    cudaGetSymbolAddress((void**)&kp,  g_k);
    cudaGetSymbolAddress((void**)&ap,  g_attn);
    cudaGetSymbolAddress((void**)&xr,  g_xr);
    cudaGetSymbolAddress((void**)&wvr, g_wvr);
    cudaGetSymbolAddress((void**)&wor, g_wor);
    cudaGetSymbolAddress((void**)&po,  g_po);
    cudaGetSymbolAddress((void**)&pl,  g_pl);
    cudaGetSymbolAddress((void**)&qh,  g_qh);
    cudaGetSymbolAddress((void**)&kh,  g_kh);
    cudaGetSymbolAddress((void**)&vh,  g_vh);
    cudaGetSymbolAddress((void**)&xh,  g_xh);
    cudaGetSymbolAddress((void**)&whq, g_whq);
    cudaGetSymbolAddress((void**)&whk, g_whk);

    cudaFuncSetAttribute(qkv_kernel, cudaFuncAttributeMaxDynamicSharedMemorySize, GSMEM);
    cudaFuncSetAttribute(wo_kernel,  cudaFuncAttributeMaxDynamicSharedMemorySize, WOSMEM);
    cudaFuncSetAttribute(attn_mma,   cudaFuncAttributeMaxDynamicSharedMemorySize, ATT_SMEM);

    prologue<<<1216, 256>>>(x, wq, wk, wv, wo, kc, vc);

    qkv_kernel<<<dim3(36, 13), 256, GSMEM>>>(
        xh, whq, whk, xr, wvr, bq, bk, bv,
        qp, kp, vh + (size_t)START * DIM);

    const float qscale = 0.08838834764831845f * 1.4426950408889634f;  // 1/sqrt(d)*log2(e)
    norm_rope2<<<dim3(SEQ, 2), 256>>>(qp, kp, nq_w, nk_w, freqs,
                                      qh, kh + (size_t)START * DIM, qscale);

    attn_mma<<<dim3(SEQ_PAD / 64, NH, NSPLIT), 128, ATT_SMEM>>>(kh, vh, qh, po, pl);

    combine_kernel<<<SEQ, 256>>>(po, pl, ap);

    wo_kernel<<<dim3(12, 25), 256, WOSMEM>>>(ap, wor, bo, out);
}